// round 16
// baseline (speedup 1.0000x reference)
#include <cuda_runtime.h>

#define W56   56
#define HW    3136
#define WC_N  32
#define C_N   256
#define GRP   8
#define LW    16     // lanes per image row (14 active + 2 idle)
#define RPB   8      // rows per block
#define NTHR  (LW * RPB)   // 128

__device__ __forceinline__ float4 zf4() { return make_float4(0.f, 0.f, 0.f, 0.f); }

__device__ __forceinline__ float getc(const float4& v, int i) {
    switch (i) { case 0: return v.x; case 1: return v.y; case 2: return v.z; default: return v.w; }
}
__device__ __forceinline__ void addc(float4& v, int i, float a) {
    switch (i) { case 0: v.x += a; break; case 1: v.y += a; break;
                 case 2: v.z += a; break; default: v.w += a; break; }
}

// ---------- D<=2 path: halo via shfl from neighbor lanes ----------
template<int D>
struct Win {
    float4 M;
    float  Lc[2];   // Lc[k] = pixel w4 - D + k
    float  Rc[2];   // Rc[k] = pixel w4 + 4 + k
};

template<int D>
__device__ __forceinline__ Win<D> make_win(float4 M, bool lv, bool rvx) {
    Win<D> w; w.M = M;
#pragma unroll
    for (int k = 0; k < D; k++) {
        float l = __shfl_up_sync  (0xffffffffu, getc(M, 4 - D + k), 1, LW);
        float r = __shfl_down_sync(0xffffffffu, getc(M, k),         1, LW);
        w.Lc[k] = lv  ? l : 0.f;
        w.Rc[k] = rvx ? r : 0.f;
    }
    return w;
}

template<int D>
__device__ __forceinline__ float wat(const Win<D>& w, int I) {   // I compile-time const
    if (I < 4)      return w.Lc[I - (4 - D)];
    else if (I < 8) return getc(w.M, I - 4);
    else            return w.Rc[I - 8];
}

template<int D>
__device__ __forceinline__ void wfma(float4& acc, const float4& wk, const Win<D>& a, int c) {
#pragma unroll
    for (int i = 0; i < 4; i++)
        addc(acc, i, getc(wk, i) * wat<D>(a, 4 + i + c));
}

// ---------- D>=3 path: halo via direct aligned float4 loads ----------
struct Row3 { float4 L, M, R; };   // 12-float window [w4-4, w4+8)

__device__ __forceinline__ float rat(const Row3& r, int I) {     // I compile-time const
    if (I < 4)      return getc(r.L, I);
    else if (I < 8) return getc(r.M, I - 4);
    else            return getc(r.R, I - 8);
}

__device__ __forceinline__ void rfma(float4& acc, const float4& wk, const Row3& a, int c) {
#pragma unroll
    for (int i = 0; i < 4; i++)
        addc(acc, i, getc(wk, i) * rat(a, 4 + i + c));
}

template<int D>
__device__ __forceinline__ void lcd_body(const float* __restrict__ x,
                                         const float* __restrict__ weight,
                                         float* __restrict__ out,
                                         int b, int wc, int h, int w4, bool active)
{
    // 9 taps x 4 pixels of weights in registers (streaming read: zero reuse)
    float4 wg[9];
    if (active) {
        const float4* wp = (const float4*)(weight + ((size_t)(b * WC_N + wc) * 9) * HW + h * W56 + w4);
#pragma unroll
        for (int k = 0; k < 9; k++) wg[k] = __ldcs(wp + k * (HW / 4));
    } else {
#pragma unroll
        for (int k = 0; k < 9; k++) wg[k] = zf4();
    }

    const bool lv = (w4 > 0), rvx = (w4 < 52);
    bool rv[3];
    int  roff[3];
#pragma unroll
    for (int j = 0; j < 3; j++) {
        const int hh = h + (j - 1) * D;
        rv[j]   = ((unsigned)hh < (unsigned)W56) && active;
        roff[j] = (hh * W56 + w4) / 4;   // float4 index
    }

    const float4* xb = (const float4*)(x + (size_t)(b * C_N + wc) * HW);
    float*        ob = out + (size_t)(b * C_N + wc) * HW + h * W56 + w4;

#pragma unroll 1
    for (int g = 0; g < GRP; g += 2) {
        const float4* xp0 = xb + (size_t)g * WC_N * (HW / 4);
        const float4* xp1 = xp0 + (size_t)WC_N * (HW / 4);
        float4 acc0 = zf4(), acc1 = zf4();

        if constexpr (D <= 2) {
            // 6 LDG + 12*D shfl per pair
            float4 M0[3], M1[3];
#pragma unroll
            for (int j = 0; j < 3; j++) {
                M0[j] = rv[j] ? __ldg(xp0 + roff[j]) : zf4();
                M1[j] = rv[j] ? __ldg(xp1 + roff[j]) : zf4();
            }
#pragma unroll
            for (int j = 0; j < 3; j++) {
                Win<D> a0 = make_win<D>(M0[j], lv, rvx);
                Win<D> a1 = make_win<D>(M1[j], lv, rvx);
#pragma unroll
                for (int kw = 0; kw < 3; kw++) {
                    const int c = (kw - 1) * D;
                    wfma<D>(acc0, wg[j * 3 + kw], a0, c);
                    wfma<D>(acc1, wg[j * 3 + kw], a1, c);
                }
            }
        } else {
            // 18 LDG per pair, zero shfl (per-j batching keeps live set small)
#pragma unroll
            for (int j = 0; j < 3; j++) {
                const bool v = rv[j];
                Row3 a0, a1;
                a0.L = (v && lv)  ? __ldg(xp0 + roff[j] - 1) : zf4();
                a0.M =  v         ? __ldg(xp0 + roff[j])     : zf4();
                a0.R = (v && rvx) ? __ldg(xp0 + roff[j] + 1) : zf4();
                a1.L = (v && lv)  ? __ldg(xp1 + roff[j] - 1) : zf4();
                a1.M =  v         ? __ldg(xp1 + roff[j])     : zf4();
                a1.R = (v && rvx) ? __ldg(xp1 + roff[j] + 1) : zf4();
#pragma unroll
                for (int kw = 0; kw < 3; kw++) {
                    const int c = (kw - 1) * D;
                    rfma(acc0, wg[j * 3 + kw], a0, c);
                    rfma(acc1, wg[j * 3 + kw], a1, c);
                }
            }
        }

        if (active) {
            __stcs((float4*)(ob + (size_t)g * WC_N * HW),       acc0);
            __stcs((float4*)(ob + (size_t)(g + 1) * WC_N * HW), acc1);
        }
    }
}

__global__ __launch_bounds__(NTHR)
void lcd_kernel(const float* __restrict__ x,
                const float* __restrict__ weight,
                const int*   __restrict__ dilation,
                float*       __restrict__ out)
{
    const int tx = threadIdx.x;            // 0..15 (lane within row)
    const int ty = threadIdx.y;            // 0..7  (row within strip)
    const int wc = blockIdx.y;
    const int b  = blockIdx.z;
    const int h  = blockIdx.x * RPB + ty;  // 0..55
    const int w4 = tx * 4;
    const bool active = (tx < 14);

    const int d = __ldg(&dilation[wc]);    // 1..4, uniform per block -> no divergence

    switch (d) {
        case 1:  lcd_body<1>(x, weight, out, b, wc, h, w4, active); break;
        case 2:  lcd_body<2>(x, weight, out, b, wc, h, w4, active); break;
        case 3:  lcd_body<3>(x, weight, out, b, wc, h, w4, active); break;
        default: lcd_body<4>(x, weight, out, b, wc, h, w4, active); break;
    }
}

extern "C" void kernel_launch(void* const* d_in, const int* in_sizes, int n_in,
                              void* d_out, int out_size)
{
    const float* x        = (const float*)d_in[0];
    const float* weight   = (const float*)d_in[1];
    const int*   dilation = (const int*)d_in[2];
    float*       out      = (float*)d_out;

    dim3 grid(W56 / RPB, WC_N, 8);   // (7, 32, 8)
    dim3 block(LW, RPB);             // 128 threads
    lcd_kernel<<<grid, block>>>(x, weight, dilation, out);
}

// round 17
// speedup vs baseline: 1.0140x; 1.0140x over previous
#include <cuda_runtime.h>

#define W56   56
#define HW    3136
#define HW4   784          // float4 per channel image
#define WC_N  32
#define C_N   256
#define GRP   8
#define LW    16           // lanes per image row (14 active + 2 idle)
#define NTHR  896          // 16 x 56 = whole image

__device__ __forceinline__ float4 zf4() { return make_float4(0.f, 0.f, 0.f, 0.f); }

__device__ __forceinline__ float getc(const float4& v, int i) {
    switch (i) { case 0: return v.x; case 1: return v.y; case 2: return v.z; default: return v.w; }
}
__device__ __forceinline__ void addc(float4& v, int i, float a) {
    switch (i) { case 0: v.x += a; break; case 1: v.y += a; break;
                 case 2: v.z += a; break; default: v.w += a; break; }
}

// Logical 12-float window [w4-4, w4+8); halo words via shfl from neighbor lanes.
template<int D>
struct Win {
    float4 M;
    float  Lc[4];
    float  Rc[4];
};

template<int D>
__device__ __forceinline__ Win<D> make_win(float4 M, bool lv, bool rvx) {
    Win<D> w; w.M = M;
#pragma unroll
    for (int k = 0; k < D; k++) {
        float l = __shfl_up_sync  (0xffffffffu, getc(M, 4 - D + k), 1, LW);
        float r = __shfl_down_sync(0xffffffffu, getc(M, k),         1, LW);
        w.Lc[k] = lv  ? l : 0.f;
        w.Rc[k] = rvx ? r : 0.f;
    }
    return w;
}

template<int D>
__device__ __forceinline__ float wat(const Win<D>& w, int I) {   // I compile-time const
    if (I < 4)      return w.Lc[I - (4 - D)];
    else if (I < 8) return getc(w.M, I - 4);
    else            return w.Rc[I - 8];
}

template<int D>
__device__ __forceinline__ void wfma(float4& acc, const float4& wk, const Win<D>& a, int c) {
#pragma unroll
    for (int i = 0; i < 4; i++)
        addc(acc, i, getc(wk, i) * wat<D>(a, 4 + i + c));
}

__device__ __forceinline__ void cp_issue(float4* dst, const float4* src, bool pred) {
    if (pred) {
        unsigned sa = (unsigned)__cvta_generic_to_shared(dst);
        asm volatile("cp.async.cg.shared.global [%0], [%1], 16;" :: "r"(sa), "l"(src) : "memory");
    }
}
__device__ __forceinline__ void cp_commit() {
    asm volatile("cp.async.commit_group;" ::: "memory");
}
__device__ __forceinline__ void cp_wait1() {
    asm volatile("cp.async.wait_group 1;" ::: "memory");
}

template<int D>
__device__ __forceinline__ void lcd_body(float4 (&tile)[3][HW4],
                                         const float4* __restrict__ xb,   // x channel (b, wc), float4 units
                                         const float4* __restrict__ wp,   // weight base, stride HW4 per tap
                                         float4* __restrict__ ob,         // out base (g=0), stride 32*HW4 per g
                                         int tid, int tx, int h, bool active)
{
    // 9 taps x 4 pixels of weights in registers (streaming: zero reuse)
    float4 wg[9];
    if (active) {
#pragma unroll
        for (int k = 0; k < 9; k++) wg[k] = __ldcs(wp + k * HW4);
    } else {
#pragma unroll
        for (int k = 0; k < 9; k++) wg[k] = zf4();
    }

    const bool lv = (tx > 0), rvx = (tx < 13);
    bool rv[3];
    int  soff[3];
#pragma unroll
    for (int j = 0; j < 3; j++) {
        const int hh = h + (j - 1) * D;
        rv[j]   = ((unsigned)hh < (unsigned)W56) && active;
        soff[j] = hh * 14 + tx;          // float4 index within tile
    }

    const bool ld = (tid < HW4);
    int cur = 0;                          // ring index of tile g

#pragma unroll 1
    for (int g = 0; g < GRP; g++) {
        cp_wait1();                       // own groups: tile g landed (<=1 pending)
        __syncthreads();                  // tile g visible block-wide; buf (g-1)%3 free
        {
            const int nx = (cur + 2 >= 3) ? cur - 1 : cur + 2;   // (g+2) % 3
            cp_issue(&tile[nx][tid], xb + (size_t)(g + 2) * WC_N * HW4 + tid,
                     ld && (g + 2 < GRP));
            cp_commit();                  // empty group at tail keeps the count
        }

        float4 acc = zf4();
#pragma unroll
        for (int j = 0; j < 3; j++) {
            float4 M = rv[j] ? tile[cur][soff[j]] : zf4();
            Win<D> a = make_win<D>(M, lv, rvx);
#pragma unroll
            for (int kw = 0; kw < 3; kw++)
                wfma<D>(acc, wg[j * 3 + kw], a, (kw - 1) * D);
        }
        if (active)
            __stcs(ob + (size_t)g * WC_N * HW4, acc);

        cur = (cur + 1 >= 3) ? 0 : cur + 1;
    }
}

__global__ __launch_bounds__(NTHR)
void lcd_kernel(const float* __restrict__ x,
                const float* __restrict__ weight,
                const int*   __restrict__ dilation,
                float*       __restrict__ out)
{
    __shared__ float4 tile[3][HW4];      // 3 x 12.25 KB = 36.75 KB

    const int tx  = threadIdx.x;         // 0..15
    const int ty  = threadIdx.y;         // 0..55 = h
    const int tid = ty * LW + tx;
    const int wc  = blockIdx.x;          // 0..31
    const int b   = blockIdx.y;          // 0..7
    const int h   = ty;
    const bool active = (tx < 14);
    const bool ld = (tid < HW4);

    const float4* xb = (const float4*)x + (size_t)(b * C_N + wc) * HW4;

    // prologue: prefetch tiles g=0, g=1
    cp_issue(&tile[0][tid], xb + tid, ld);
    cp_commit();
    cp_issue(&tile[1][tid], xb + (size_t)WC_N * HW4 + tid, ld);
    cp_commit();

    const float4* wp = (const float4*)(weight + ((size_t)(b * WC_N + wc) * 9) * HW
                                       + h * W56 + tx * 4);
    float4* ob = (float4*)(out + (size_t)(b * C_N + wc) * HW + h * W56 + tx * 4);

    const int d = __ldg(&dilation[wc]);  // 1..4, uniform per block

    switch (d) {
        case 1:  lcd_body<1>(tile, xb, wp, ob, tid, tx, h, active); break;
        case 2:  lcd_body<2>(tile, xb, wp, ob, tid, tx, h, active); break;
        case 3:  lcd_body<3>(tile, xb, wp, ob, tid, tx, h, active); break;
        default: lcd_body<4>(tile, xb, wp, ob, tid, tx, h, active); break;
    }
}

extern "C" void kernel_launch(void* const* d_in, const int* in_sizes, int n_in,
                              void* d_out, int out_size)
{
    const float* x        = (const float*)d_in[0];
    const float* weight   = (const float*)d_in[1];
    const int*   dilation = (const int*)d_in[2];
    float*       out      = (float*)d_out;

    dim3 grid(WC_N, 8);        // (32, 8) = 256 blocks, one per (b, wc)
    dim3 block(LW, W56);       // 896 threads = whole image
    lcd_kernel<<<grid, block>>>(x, weight, dilation, out);
}